// round 7
// baseline (speedup 1.0000x reference)
#include <cuda_runtime.h>
#include <cuda_bf16.h>
#include <math.h>
#include <float.h>
#include <stdint.h>

#define N_ROWS 100000
#define DDIM 1024
#define ADIM 128
#define HDIM 256
#define KSEL 16
#define MAXC 4096
#define NHIST 8192
#define HSHIFT 19
#define CUSH 256u
#define GEMM_BLKS 782       // ceil(100000/128)
#define WSCALE 16.0f
#define WINV   0.0625f

// ================= scratch (device globals; no allocation) =================
__device__ float g_scores[N_ROWS];
__device__ __align__(16) unsigned char g_Bfp8[ADIM * DDIM];  // Wa1^T * 16, e4m3, [n][k]
__device__ unsigned g_hist[NHIST];
__device__ int      g_ncand;
__device__ unsigned g_thresh;
__device__ int      g_cand_i[MAXC];
__device__ float    g_cand_v[MAXC];
__device__ int      g_topidx[KSEL];
__device__ float    g_attnw[KSEL];
__device__ float    g_emb[DDIM];

__device__ __forceinline__ uint32_t smem_u32(const void* p) {
    uint32_t a;
    asm("{ .reg .u64 tmp; cvta.to.shared.u64 tmp, %1; cvt.u32.u64 %0, tmp; }"
        : "=r"(a) : "l"(p));
    return a;
}

__device__ __forceinline__ unsigned fliporder(float f) {
    unsigned u = __float_as_uint(f);
    return (u & 0x80000000u) ? ~u : (u | 0x80000000u);
}

// pack float4 -> 4 e4m3 bytes (v.x lowest byte)
__device__ __forceinline__ uint32_t pack4_e4m3(float4 v) {
    uint32_t r;
    asm("{\n\t.reg .b16 l, h;\n\t"
        "cvt.rn.satfinite.e4m3x2.f32 l, %2, %1;\n\t"
        "cvt.rn.satfinite.e4m3x2.f32 h, %4, %3;\n\t"
        "mov.b32 %0, {l, h};\n\t}"
        : "=r"(r) : "f"(v.x), "f"(v.y), "f"(v.z), "f"(v.w));
    return r;
}

// ================= pre-pass: Wa1 [k][n] fp32 -> g_Bfp8 [n][k] e4m3 (x16) =================
__global__ void __launch_bounds__(256) conv_B(const float* __restrict__ Wa1) {
    int idx = blockIdx.x * 256 + threadIdx.x;   // 0..65535
    int n  = idx >> 9;                          // 0..127
    int kp = idx & 511;                         // 0..511 -> k = 2kp, 2kp+1
    float v0 = Wa1[(size_t)(2 * kp    ) * ADIM + n] * WSCALE;
    float v1 = Wa1[(size_t)(2 * kp + 1) * ADIM + n] * WSCALE;
    uint16_t u;
    asm("cvt.rn.satfinite.e4m3x2.f32 %0, %2, %1;" : "=h"(u) : "f"(v0), "f"(v1));
    *(uint16_t*)(g_Bfp8 + (size_t)n * DDIM + 2 * kp) = u;
}

// ================= zero: full_weights + histogram + counter + logit seed =================
__global__ void __launch_bounds__(256) zero_misc(float* __restrict__ out,
                                                 const float* __restrict__ bc2) {
    int i = blockIdx.x * 256 + threadIdx.x;
    if (i < N_ROWS) out[1 + DDIM + i] = 0.f;
    if (i < NHIST)  g_hist[i] = 0u;
    if (i == 0)   { g_ncand = 0; out[0] = bc2[0]; }
}

// ================= main GEMM: approx scores via mma.sync e4m3 =================
// BM=128, BN=128(=ADIM), BK=32 (one k32 mma step per chunk), 256 threads = 8 warps
// (2 M-halves x 4 N-slices), warp tile 64x32, double-buffered, 1 sync/chunk, 2 CTAs/SM.
#define SROWB 48   // padded row stride in BYTES (32 data + 16 pad); ldmatrix conflict-free

__global__ void __launch_bounds__(256, 2) gemm_scores(
    const float* __restrict__ x, const float* __restrict__ ba1,
    const float* __restrict__ Wa2, const float* __restrict__ ba2)
{
    __shared__ __align__(16) unsigned char sA[2][128 * SROWB];
    __shared__ __align__(16) unsigned char sB[2][128 * SROWB];
    __shared__ float s_part[4][128];
    __shared__ float s_b1[ADIM], s_w2[ADIM];

    const int t = threadIdx.x;
    const int w = t >> 5, lane = t & 31;
    const int wm = w & 1, wn = w >> 1;
    const size_t block_m = (size_t)blockIdx.x * 128;

    if (t < ADIM) { s_b1[t] = ba1[t]; s_w2[t] = Wa2[t]; }

    // A global-load mapping: 4 slots, slot j -> row (t>>3)+32j, fp32 cols (t&7)*4..+3
    const int arow = t >> 3;                    // 0..31
    const int acol = (t & 7) * 4;               // 0..28 (fp32 col, also fp8 byte off)
    const float* xptr = x + (block_m + (size_t)arow) * DDIM + acol;
    bool aok[4];
#pragma unroll
    for (int i = 0; i < 4; i++) aok[i] = (block_m + arow + 32 * i) < N_ROWS;

    // B cp.async mapping: 1 slot: row t>>1, 16B at (t&1)*16
    const int brow = t >> 1;
    const int bb16 = (t & 1) * 16;
    const unsigned char* gB = g_Bfp8 + (size_t)brow * DDIM + bb16;

    // ldmatrix lane addressing (byte-based; same tile structure as bf16 case)
    const int arow_l = ((lane >> 3) & 1) * 8 + (lane & 7);
    const int abyte_l = ((lane >> 4) & 1) * 16;
    const int brow_l = ((lane >> 4) & 1) * 8 + (lane & 7);
    const int bbyte_l = ((lane >> 3) & 1) * 16;

    const uint32_t sa_base = smem_u32(&sA[0][0]);
    const uint32_t sb_base = smem_u32(&sB[0][0]);
    const uint32_t bufstride = 128 * SROWB;

    float acc[4][4][4];
#pragma unroll
    for (int i = 0; i < 4; i++)
#pragma unroll
        for (int j = 0; j < 4; j++)
#pragma unroll
            for (int q = 0; q < 4; q++) acc[i][j][q] = 0.f;

    // ---- prologue: A(0) -> regs, B(0) -> sB[0] ----
    float4 pa0, pa1, pa2, pa3;
    pa0 = aok[0] ? *(const float4*)(xptr)             : make_float4(0,0,0,0);
    pa1 = aok[1] ? *(const float4*)(xptr + 32 * DDIM) : make_float4(0,0,0,0);
    pa2 = aok[2] ? *(const float4*)(xptr + 64 * DDIM) : make_float4(0,0,0,0);
    pa3 = aok[3] ? *(const float4*)(xptr + 96 * DDIM) : make_float4(0,0,0,0);
    {
        uint32_t d0 = sb_base + (uint32_t)(brow * SROWB + bb16);
        asm volatile("cp.async.cg.shared.global [%0], [%1], 16;" :: "r"(d0), "l"(gB) : "memory");
        asm volatile("cp.async.commit_group;" ::: "memory");
    }

#pragma unroll 1
    for (int c = 0; c < 32; c++) {
        const int buf = c & 1;
        // 1. convert + store A(c) -> sA[buf]
        {
            unsigned char* base = &sA[buf][0];
            *(uint32_t*)(base + (arow     ) * SROWB + acol) = pack4_e4m3(pa0);
            *(uint32_t*)(base + (arow + 32) * SROWB + acol) = pack4_e4m3(pa1);
            *(uint32_t*)(base + (arow + 64) * SROWB + acol) = pack4_e4m3(pa2);
            *(uint32_t*)(base + (arow + 96) * SROWB + acol) = pack4_e4m3(pa3);
        }
        // 2. LDG A(c+1)
        if (c < 31) {
            const int k0 = (c + 1) * 32;
            pa0 = aok[0] ? *(const float4*)(xptr + k0)             : make_float4(0,0,0,0);
            pa1 = aok[1] ? *(const float4*)(xptr + 32 * DDIM + k0) : make_float4(0,0,0,0);
            pa2 = aok[2] ? *(const float4*)(xptr + 64 * DDIM + k0) : make_float4(0,0,0,0);
            pa3 = aok[3] ? *(const float4*)(xptr + 96 * DDIM + k0) : make_float4(0,0,0,0);
        }
        // 3. wait B(c)
        asm volatile("cp.async.wait_group 0;" ::: "memory");
        // 4. single barrier
        __syncthreads();
        // 5. issue B(c+1) -> sB[buf^1]
        if (c < 31) {
            const int k0 = (c + 1) * 32;
            uint32_t d0 = sb_base + (uint32_t)(buf ^ 1) * bufstride
                        + (uint32_t)(brow * SROWB + bb16);
            asm volatile("cp.async.cg.shared.global [%0], [%1], 16;" :: "r"(d0), "l"(gB + k0) : "memory");
            asm volatile("cp.async.commit_group;" ::: "memory");
        }
        // 6. compute chunk c: one K=32 fp8 mma step
        const uint32_t sa = sa_base + buf * bufstride;
        const uint32_t sb = sb_base + buf * bufstride;
        uint32_t b[4][2];
#pragma unroll
        for (int njp = 0; njp < 2; njp++) {
            uint32_t addr = sb + (uint32_t)((wn * 32 + njp * 16 + brow_l) * SROWB + bbyte_l);
            uint32_t r0, r1, r2, r3;
            asm volatile("ldmatrix.sync.aligned.m8n8.x4.shared.b16 {%0,%1,%2,%3}, [%4];"
                : "=r"(r0), "=r"(r1), "=r"(r2), "=r"(r3) : "r"(addr));
            b[njp * 2 + 0][0] = r0; b[njp * 2 + 0][1] = r1;
            b[njp * 2 + 1][0] = r2; b[njp * 2 + 1][1] = r3;
        }
        uint32_t a[4][4];
#pragma unroll
        for (int mi = 0; mi < 4; mi++) {
            uint32_t addr = sa + (uint32_t)((wm * 64 + mi * 16 + arow_l) * SROWB + abyte_l);
            asm volatile("ldmatrix.sync.aligned.m8n8.x4.shared.b16 {%0,%1,%2,%3}, [%4];"
                : "=r"(a[mi][0]), "=r"(a[mi][1]), "=r"(a[mi][2]), "=r"(a[mi][3]) : "r"(addr));
        }
#pragma unroll
        for (int mi = 0; mi < 4; mi++)
#pragma unroll
            for (int nj = 0; nj < 4; nj++) {
                asm volatile(
                    "mma.sync.aligned.m16n8k32.row.col.f32.e4m3.e4m3.f32 "
                    "{%0,%1,%2,%3}, {%4,%5,%6,%7}, {%8,%9}, {%0,%1,%2,%3};"
                    : "+f"(acc[mi][nj][0]), "+f"(acc[mi][nj][1]),
                      "+f"(acc[mi][nj][2]), "+f"(acc[mi][nj][3])
                    : "r"(a[mi][0]), "r"(a[mi][1]), "r"(a[mi][2]), "r"(a[mi][3]),
                      "r"(b[nj][0]), "r"(b[nj][1]));
            }
    }

    // ---- epilogue: score = sum_n tanh(acc/16 + b1[n]) * w2[n], fused histogram ----
    __syncthreads();
#pragma unroll
    for (int mi = 0; mi < 4; mi++) {
        float p0 = 0.f, p1 = 0.f;
#pragma unroll
        for (int nj = 0; nj < 4; nj++) {
            int col = wn * 32 + nj * 8 + (lane & 3) * 2;
            float th;
            float v0 = fmaf(acc[mi][nj][0], WINV, s_b1[col]);
            asm("tanh.approx.f32 %0, %1;" : "=f"(th) : "f"(v0));
            p0 = fmaf(th, s_w2[col], p0);
            float v1 = fmaf(acc[mi][nj][1], WINV, s_b1[col + 1]);
            asm("tanh.approx.f32 %0, %1;" : "=f"(th) : "f"(v1));
            p0 = fmaf(th, s_w2[col + 1], p0);
            float v2 = fmaf(acc[mi][nj][2], WINV, s_b1[col]);
            asm("tanh.approx.f32 %0, %1;" : "=f"(th) : "f"(v2));
            p1 = fmaf(th, s_w2[col], p1);
            float v3 = fmaf(acc[mi][nj][3], WINV, s_b1[col + 1]);
            asm("tanh.approx.f32 %0, %1;" : "=f"(th) : "f"(v3));
            p1 = fmaf(th, s_w2[col + 1], p1);
        }
        p0 += __shfl_xor_sync(0xffffffffu, p0, 1);
        p0 += __shfl_xor_sync(0xffffffffu, p0, 2);
        p1 += __shfl_xor_sync(0xffffffffu, p1, 1);
        p1 += __shfl_xor_sync(0xffffffffu, p1, 2);
        if ((lane & 3) == 0) {
            int r = wm * 64 + mi * 16 + (lane >> 2);
            s_part[wn][r]     = p0;
            s_part[wn][r + 8] = p1;
        }
    }
    __syncthreads();
    if (t < 128) {
        size_t m = block_m + (size_t)t;
        if (m < N_ROWS) {
            float sc = s_part[0][t] + s_part[1][t] + s_part[2][t] + s_part[3][t] + ba2[0];
            g_scores[m] = sc;
            atomicAdd(&g_hist[fliporder(sc) >> HSHIFT], 1u);
        }
    }
}

// ================= threshold scan (8192 bins, cushion 256) =================
__global__ void __launch_bounds__(256) scan_k() {
    __shared__ unsigned part[256];
    __shared__ unsigned segbins[32];
    __shared__ int s_seg;
    __shared__ unsigned s_cum;
    int t = threadIdx.x;
    unsigned sum = 0;
#pragma unroll
    for (int j = 0; j < 32; j++) sum += g_hist[t * 32 + j];
    part[t] = sum;
    __syncthreads();
    if (t == 0) {
        unsigned cum = 0; int seg = 255;
        for (; seg > 0; seg--) { if (cum + part[seg] >= CUSH) break; cum += part[seg]; }
        s_seg = seg; s_cum = cum;
    }
    __syncthreads();
    if (t < 32) segbins[t] = g_hist[s_seg * 32 + t];
    __syncthreads();
    if (t == 0) {
        unsigned cum = s_cum; int b = 31;
        for (; b > 0; b--) { cum += segbins[b]; if (cum >= CUSH) break; }
        g_thresh = ((unsigned)(s_seg * 32 + b)) << HSHIFT;
    }
}

__global__ void __launch_bounds__(512) collect_k() {
    int i = blockIdx.x * 512 + threadIdx.x;
    if (i < N_ROWS && fliporder(g_scores[i]) >= g_thresh) {
        int p = atomicAdd(&g_ncand, 1);
        if (p < MAXC) g_cand_i[p] = i;
    }
}

// ================= exact fp32 rescore, 4 candidates per Wa1 pass =================
__global__ void __launch_bounds__(128) rescore_k(
    const float* __restrict__ x, const float* __restrict__ Wa1,
    const float* __restrict__ ba1, const float* __restrict__ Wa2,
    const float* __restrict__ ba2)
{
    __shared__ __align__(16) float sx[DDIM][4];   // [k][cand]
    __shared__ float sred[4][4];
    int nc = g_ncand; if (nc > MAXC) nc = MAXC;
    int ngr = (nc + 3) >> 2;
    const int t = threadIdx.x;
    for (int g = blockIdx.x; g < ngr; g += gridDim.x) {
        int cid[4];
#pragma unroll
        for (int ci = 0; ci < 4; ci++) {
            int c = g * 4 + ci;
            cid[ci] = (c < nc) ? g_cand_i[c] : g_cand_i[0];
        }
#pragma unroll
        for (int ci = 0; ci < 4; ci++)
            for (int j = t; j < DDIM; j += 128)
                sx[j][ci] = x[(size_t)cid[ci] * DDIM + j];
        __syncthreads();
        float a0 = 0.f, a1 = 0.f, a2 = 0.f, a3 = 0.f;
#pragma unroll 4
        for (int k = 0; k < DDIM; k++) {
            float wv = Wa1[(size_t)k * ADIM + t];
            float4 xv = *(const float4*)&sx[k][0];
            a0 = fmaf(xv.x, wv, a0);
            a1 = fmaf(xv.y, wv, a1);
            a2 = fmaf(xv.z, wv, a2);
            a3 = fmaf(xv.w, wv, a3);
        }
        float w2 = Wa2[t], b1 = ba1[t];
        float v0 = tanhf(a0 + b1) * w2;
        float v1 = tanhf(a1 + b1) * w2;
        float v2 = tanhf(a2 + b1) * w2;
        float v3 = tanhf(a3 + b1) * w2;
#pragma unroll
        for (int off = 16; off >= 1; off >>= 1) {
            v0 += __shfl_down_sync(0xffffffffu, v0, off);
            v1 += __shfl_down_sync(0xffffffffu, v1, off);
            v2 += __shfl_down_sync(0xffffffffu, v2, off);
            v3 += __shfl_down_sync(0xffffffffu, v3, off);
        }
        if ((t & 31) == 0) {
            sred[t >> 5][0] = v0; sred[t >> 5][1] = v1;
            sred[t >> 5][2] = v2; sred[t >> 5][3] = v3;
        }
        __syncthreads();
        if (t < 4) {
            int c = g * 4 + t;
            if (c < nc)
                g_cand_v[c] = sred[0][t] + sred[1][t] + sred[2][t] + sred[3][t] + ba2[0];
        }
        __syncthreads();
    }
}

// ================= tail: exact top-16 + softmax + scatter + embedding =================
__global__ void __launch_bounds__(256) tail_k(const float* __restrict__ x,
                                              float* __restrict__ out) {
    __shared__ float sv[MAXC];
    __shared__ int   si[MAXC];
    __shared__ float wv[8];
    __shared__ int   wi[8];
    __shared__ float topv[KSEL];
    __shared__ int   topi[KSEL];
    __shared__ float topw[KSEL];
    const int t = threadIdx.x;
    int nc = g_ncand; if (nc > MAXC) nc = MAXC;
    for (int i = t; i < nc; i += 256) { sv[i] = g_cand_v[i]; si[i] = g_cand_i[i]; }
    __syncthreads();
    for (int it = 0; it < KSEL; it++) {
        float bv = -FLT_MAX; int bi = 0x7fffffff;
        for (int i = t; i < nc; i += 256) {
            float v = sv[i]; int gi = si[i];
            if (v > bv || (v == bv && gi < bi)) { bv = v; bi = gi; }
        }
#pragma unroll
        for (int off = 16; off >= 1; off >>= 1) {
            float ov = __shfl_down_sync(0xffffffffu, bv, off);
            int   oi = __shfl_down_sync(0xffffffffu, bi, off);
            if (ov > bv || (ov == bv && oi < bi)) { bv = ov; bi = oi; }
        }
        if ((t & 31) == 0) { wv[t >> 5] = bv; wi[t >> 5] = bi; }
        __syncthreads();
        if (t == 0) {
            for (int w = 1; w < 8; w++)
                if (wv[w] > wv[0] || (wv[w] == wv[0] && wi[w] < wi[0])) { wv[0] = wv[w]; wi[0] = wi[w]; }
            topv[it] = wv[0]; topi[it] = wi[0];
        }
        __syncthreads();
        int wini = topi[it];
        for (int i = t; i < nc; i += 256)
            if (si[i] == wini) sv[i] = -FLT_MAX;
        __syncthreads();
    }
    if (t == 0) {
        float m = topv[0];
        float e[KSEL];
        float ssum = 0.f;
        for (int j = 0; j < KSEL; j++) { e[j] = expf(topv[j] - m); ssum += e[j]; }
        float inv = 1.f / ssum;
        for (int j = 0; j < KSEL; j++) {
            float wgt = e[j] * inv;
            topw[j] = wgt;
            g_attnw[j]  = wgt;
            g_topidx[j] = topi[j];
            out[1 + DDIM + N_ROWS + j] = (float)topi[j];
            out[1 + DDIM + topi[j]]    = wgt;
        }
    }
    __syncthreads();
    for (int d = t; d < DDIM; d += 256) {
        float s = 0.f;
#pragma unroll
        for (int j = 0; j < KSEL; j++)
            s += topw[j] * x[(size_t)topi[j] * DDIM + d];
        g_emb[d]   = s;
        out[1 + d] = s;
    }
}

// ================= classifier: 8 blocks, partial logits via atomicAdd =================
__global__ void __launch_bounds__(256) cls_kernel(
    const float* __restrict__ Wc1, const float* __restrict__ bc1,
    const float* __restrict__ Wc2, float* __restrict__ out)
{
    __shared__ float e[DDIM];
    __shared__ float sred[8][32];
    const int t = threadIdx.x;
    const int j = blockIdx.x * 32 + (t & 31);
    const int dp = (t >> 5) * 128;
    for (int d = t; d < DDIM; d += 256) e[d] = g_emb[d];
    __syncthreads();
    float acc = 0.f;
#pragma unroll 16
    for (int d = 0; d < 128; d++)
        acc = fmaf(e[dp + d], Wc1[(size_t)(dp + d) * HDIM + j], acc);
    sred[t >> 5][t & 31] = acc;
    __syncthreads();
    if (t < 32) {
        float a = sred[0][t] + sred[1][t] + sred[2][t] + sred[3][t]
                + sred[4][t] + sred[5][t] + sred[6][t] + sred[7][t];
        int jj = blockIdx.x * 32 + t;
        float h = fmaxf(a + bc1[jj], 0.f);
        float part = h * Wc2[jj];
#pragma unroll
        for (int off = 16; off >= 1; off >>= 1)
            part += __shfl_down_sync(0xffffffffu, part, off);
        if (t == 0) atomicAdd(out, part);
    }
}

// ================= launch =================
extern "C" void kernel_launch(void* const* d_in, const int* in_sizes, int n_in,
                              void* d_out, int out_size)
{
    const float* x   = (const float*)d_in[0];
    const float* Wa1 = (const float*)d_in[1];
    const float* ba1 = (const float*)d_in[2];
    const float* Wa2 = (const float*)d_in[3];
    const float* ba2 = (const float*)d_in[4];
    const float* Wc1 = (const float*)d_in[5];
    const float* bc1 = (const float*)d_in[6];
    const float* Wc2 = (const float*)d_in[7];
    const float* bc2 = (const float*)d_in[8];
    float* out = (float*)d_out;

    conv_B<<<256, 256>>>(Wa1);
    zero_misc<<<391, 256>>>(out, bc2);
    gemm_scores<<<GEMM_BLKS, 256>>>(x, ba1, Wa2, ba2);
    scan_k<<<1, 256>>>();
    collect_k<<<(N_ROWS + 511) / 512, 512>>>();
    rescore_k<<<128, 128>>>(x, Wa1, ba1, Wa2, ba2);
    tail_k<<<1, 256>>>(x, out);
    cls_kernel<<<HDIM / 32, 256>>>(Wc1, bc1, Wc2, out);
}